// round 9
// baseline (speedup 1.0000x reference)
#include <cuda_runtime.h>
#include <math.h>

// LogLinearAttention collapses analytically:
//   softmax over axis=1 (s) => sum_s attn[b,s,t] == 1
//   pooled[b,d] = sum_t r[b,t,d] = (sum_s x[b,s,:]) @ Wr^T + S*br
//   out[b] = sigmoid( sum_d xs[b,d]*u[d] + c ),  u = Wl @ Wr,  c = S*dot(br,Wl)+bl
// Only x (32 MiB) and Wr (1 MiB) matter.  Two kernels, each using the
// last-block pattern (atomic ticket + threadfence) so there are no separate
// combine/final launches.

#define BB 8
#define SS 2048
#define DD 512
#define D4 128               // float4 columns per row
#define JCHUNK 4             // Wr rows per block in kU
#define NJB (DD / JCHUNK)    // 128 blocks in kU
#define ROWS 16              // x rows per block in kMain
#define NCHUNK (SS / ROWS)   // 128 chunks per batch
#define NPZ (BB * NCHUNK)    // 1024 blocks in kMain

__device__ float g_pu[NJB * DD];   // per-block partial u
__device__ float g_u[DD];          // u = Wl @ Wr
__device__ float g_c;              // c = S*dot(br,Wl) + bl
__device__ float g_pz[NPZ];        // per-block scalar partial of z
__device__ unsigned int g_ctrU = 0;
__device__ unsigned int g_ctrM = 0;

// ---------------------------------------------------------------------------
// kU: block jb computes partial u over 4 Wr rows; the LAST block to finish
// folds all partials (256 KiB, L2-hot) into g_u, computes g_c, resets ctr.
// ---------------------------------------------------------------------------
__global__ void __launch_bounds__(128) kU(const float* __restrict__ Wr,
                                          const float* __restrict__ Wl,
                                          const float* __restrict__ br,
                                          const float* __restrict__ bl) {
    const int jb = blockIdx.x;
    const int t  = threadIdx.x;

    float4 acc = make_float4(0.f, 0.f, 0.f, 0.f);
#pragma unroll
    for (int jj = 0; jj < JCHUNK; ++jj) {
        const int j = jb * JCHUNK + jj;
        const float wl = __ldg(Wl + j);
        const float4 w = reinterpret_cast<const float4*>(Wr + (size_t)j * DD)[t];
        acc.x = fmaf(wl, w.x, acc.x);
        acc.y = fmaf(wl, w.y, acc.y);
        acc.z = fmaf(wl, w.z, acc.z);
        acc.w = fmaf(wl, w.w, acc.w);
    }
    reinterpret_cast<float4*>(g_pu + (size_t)jb * DD)[t] = acc;

    __threadfence();
    __shared__ int s_last;
    if (t == 0) s_last = (atomicAdd(&g_ctrU, 1u) == NJB - 1);
    __syncthreads();
    if (!s_last) return;
    __threadfence();

    // fold partials: thread t owns float4 column t (fixed order -> deterministic)
    float4 uacc = make_float4(0.f, 0.f, 0.f, 0.f);
#pragma unroll 8
    for (int b2 = 0; b2 < NJB; ++b2) {
        const float4 p = reinterpret_cast<const float4*>(g_pu + (size_t)b2 * DD)[t];
        uacc.x += p.x; uacc.y += p.y; uacc.z += p.z; uacc.w += p.w;
    }
    reinterpret_cast<float4*>(g_u)[t] = uacc;

    // c = S * dot(br, Wl) + bl   (512-elem dot with 128 threads)
    float p = br[t]           * Wl[t]
            + br[t + 128]     * Wl[t + 128]
            + br[t + 256]     * Wl[t + 256]
            + br[t + 384]     * Wl[t + 384];
#pragma unroll
    for (int off = 16; off > 0; off >>= 1)
        p += __shfl_xor_sync(0xffffffffu, p, off);

    __shared__ float sdot[4];
    if ((t & 31) == 0) sdot[t >> 5] = p;
    __syncthreads();
    if (t == 0) {
        g_c = (float)SS * ((sdot[0] + sdot[1]) + (sdot[2] + sdot[3])) + bl[0];
        g_ctrU = 0;   // reset for next graph replay
    }
}

// ---------------------------------------------------------------------------
// kMain: the 32 MiB streaming pass. 1024 blocks x 128 threads; each thread
// 16 independent float4 loads (MLP=16) dotted with u, block-reduce to one
// scalar. The LAST block reduces the 1024 scalars (4 KiB, L2-hit), applies
// sigmoid, writes out, resets ctr.
// ---------------------------------------------------------------------------
__global__ void __launch_bounds__(128) kMain(const float* __restrict__ x,
                                             float* __restrict__ out) {
    const int blk = blockIdx.x;
    const int b   = blk / NCHUNK;
    const int ch  = blk % NCHUNK;
    const int t   = threadIdx.x;

    const float4 uv = reinterpret_cast<const float4*>(g_u)[t];
    const float4* xp = reinterpret_cast<const float4*>(
        x + ((size_t)b * SS + (size_t)ch * ROWS) * DD);

    float4 acc = make_float4(0.f, 0.f, 0.f, 0.f);
#pragma unroll
    for (int r = 0; r < ROWS; ++r) {
        const float4 v = xp[(size_t)r * D4 + t];
        acc.x = fmaf(v.x, uv.x, acc.x);
        acc.y = fmaf(v.y, uv.y, acc.y);
        acc.z = fmaf(v.z, uv.z, acc.z);
        acc.w = fmaf(v.w, uv.w, acc.w);
    }
    float s = (acc.x + acc.y) + (acc.z + acc.w);

#pragma unroll
    for (int off = 16; off > 0; off >>= 1)
        s += __shfl_xor_sync(0xffffffffu, s, off);

    __shared__ float red[4];
    if ((t & 31) == 0) red[t >> 5] = s;
    __syncthreads();
    if (t == 0) g_pz[blk] = (red[0] + red[1]) + (red[2] + red[3]);

    __threadfence();
    __shared__ int s_last;
    if (t == 0) s_last = (atomicAdd(&g_ctrM, 1u) == NPZ - 1);
    __syncthreads();
    if (!s_last) return;
    __threadfence();

    // final: warp w handles batches 2w and 2w+1 (fixed order -> deterministic)
    const int w = t >> 5, lane = t & 31;
    const float c = g_c;
#pragma unroll
    for (int k = 0; k < 2; ++k) {
        const int bb = w * 2 + k;
        float z = 0.f;
#pragma unroll
        for (int i = lane; i < NCHUNK; i += 32) z += g_pz[bb * NCHUNK + i];
#pragma unroll
        for (int off = 16; off > 0; off >>= 1)
            z += __shfl_xor_sync(0xffffffffu, z, off);
        if (lane == 0) {
            const float zz = z + c;
            out[bb] = 1.0f / (1.0f + expf(-zz));
        }
    }
    if (t == 0) g_ctrM = 0;   // reset for next graph replay
}

// ---------------------------------------------------------------------------
// Inputs (metadata order): 0=x 1=Wq 2=bq 3=Wv 4=bv 5=Wr 6=br 7=Wl 8=bl
// Output: float32 [B]
// ---------------------------------------------------------------------------
extern "C" void kernel_launch(void* const* d_in, const int* in_sizes, int n_in,
                              void* d_out, int out_size) {
    const float* x  = (const float*)d_in[0];
    const float* Wr = (const float*)d_in[5];
    const float* br = (const float*)d_in[6];
    const float* Wl = (const float*)d_in[7];
    const float* bl = (const float*)d_in[8];
    float* out = (float*)d_out;

    kU<<<NJB, 128>>>(Wr, Wl, br, bl);
    kMain<<<NPZ, 128>>>(x, out);
}

// round 12
// speedup vs baseline: 1.0156x; 1.0156x over previous
#include <cuda_runtime.h>
#include <math.h>

// LogLinearAttention collapses analytically:
//   softmax over axis=1 (s) => sum_s attn[b,s,t] == 1
//   pooled[b,d] = sum_t r[b,t,d] = (sum_s x[b,s,:]) @ Wr^T + S*br
//   out[b] = sigmoid( sum_d xs[b,d]*u[d] + c ),  u = Wl @ Wr,  c = S*dot(br,Wl)+bl
// Only x (32 MiB) and Wr (1 MiB) matter.  Two kernels with last-block
// finalization (atomic ticket + threadfence; fixed-order sums -> deterministic).

#define BB 8
#define SS 2048
#define DD 512
#define D4 128               // float4 columns per row

// kU: 64 blocks x 128 thr, 8 Wr rows per block
#define UJ 8
#define NUB (DD / UJ)        // 64 blocks

// kMain: 1024 blocks x 256 thr, 16 x-rows per block (each thread: 8 rows, 1 col)
#define MROWS 16
#define NCHUNK (SS / MROWS)  // 128 chunks per batch
#define NPZ (BB * NCHUNK)    // 1024 blocks

__device__ float g_pu[NUB * DD];   // per-block partial u  (128 KiB)
__device__ float g_u[DD];          // u = Wl @ Wr
__device__ float g_c;              // c = S*dot(br,Wl) + bl
__device__ float g_pz[NPZ];        // per-block scalar partial of z
__device__ unsigned int g_ctrU = 0;
__device__ unsigned int g_ctrM = 0;

// ---------------------------------------------------------------------------
// kU: block jb accumulates 8 Wr rows into a 512-float partial (thread t owns
// float4 column t). Last block folds 64 partials (64 independent float4 loads
// per thread -> latency-overlapped), computes c, resets counter.
// ---------------------------------------------------------------------------
__global__ void __launch_bounds__(128) kU(const float* __restrict__ Wr,
                                          const float* __restrict__ Wl,
                                          const float* __restrict__ br,
                                          const float* __restrict__ bl) {
    const int jb = blockIdx.x;
    const int t  = threadIdx.x;

    float4 acc = make_float4(0.f, 0.f, 0.f, 0.f);
#pragma unroll
    for (int jj = 0; jj < UJ; ++jj) {
        const int j = jb * UJ + jj;
        const float wl = __ldg(Wl + j);
        const float4 w = reinterpret_cast<const float4*>(Wr + (size_t)j * DD)[t];
        acc.x = fmaf(wl, w.x, acc.x);
        acc.y = fmaf(wl, w.y, acc.y);
        acc.z = fmaf(wl, w.z, acc.z);
        acc.w = fmaf(wl, w.w, acc.w);
    }
    reinterpret_cast<float4*>(g_pu + (size_t)jb * DD)[t] = acc;

    __threadfence();
    __shared__ int s_last;
    if (t == 0) s_last = (atomicAdd(&g_ctrU, 1u) == NUB - 1);
    __syncthreads();
    if (!s_last) return;
    __threadfence();

    // fold 64 partials; fixed order -> deterministic
    float4 uacc = make_float4(0.f, 0.f, 0.f, 0.f);
#pragma unroll 16
    for (int p = 0; p < NUB; ++p) {
        const float4 v = reinterpret_cast<const float4*>(g_pu + (size_t)p * DD)[t];
        uacc.x += v.x; uacc.y += v.y; uacc.z += v.z; uacc.w += v.w;
    }
    reinterpret_cast<float4*>(g_u)[t] = uacc;

    // c = S * dot(br, Wl) + bl  (512-elem dot, 128 threads)
    float pr = br[t]       * Wl[t]
             + br[t + 128] * Wl[t + 128]
             + br[t + 256] * Wl[t + 256]
             + br[t + 384] * Wl[t + 384];
#pragma unroll
    for (int off = 16; off > 0; off >>= 1)
        pr += __shfl_xor_sync(0xffffffffu, pr, off);

    __shared__ float sdot[4];
    if ((t & 31) == 0) sdot[t >> 5] = pr;
    __syncthreads();
    if (t == 0) {
        g_c = (float)SS * ((sdot[0] + sdot[1]) + (sdot[2] + sdot[3])) + bl[0];
        g_ctrU = 0;   // reset for next graph replay
    }
}

// ---------------------------------------------------------------------------
// kMain: 32 MiB streaming pass.  1024 blocks x 256 threads (8192 warps ->
// ~86% occ).  Thread t owns float4 column (t&127), rows sub*8..sub*8+7 of its
// 16-row chunk: 8 independent float4 loads.  Block-reduce -> g_pz[blk].
// Last block reduces 1024 scalars (4 KiB L2-hit), sigmoid, writes out.
// ---------------------------------------------------------------------------
__global__ void __launch_bounds__(256) kMain(const float* __restrict__ x,
                                             float* __restrict__ out) {
    const int blk = blockIdx.x;
    const int b   = blk >> 7;          // / NCHUNK
    const int ch  = blk & (NCHUNK - 1);
    const int t   = threadIdx.x;
    const int col = t & (D4 - 1);
    const int sub = t >> 7;            // 0 or 1: which 8-row half

    const float4 uv = reinterpret_cast<const float4*>(g_u)[col];
    const float4* xp = reinterpret_cast<const float4*>(
        x + ((size_t)b * SS + (size_t)ch * MROWS + (size_t)sub * 8) * DD);

    float4 acc = make_float4(0.f, 0.f, 0.f, 0.f);
#pragma unroll
    for (int r = 0; r < 8; ++r) {
        const float4 v = xp[(size_t)r * D4 + col];
        acc.x = fmaf(v.x, uv.x, acc.x);
        acc.y = fmaf(v.y, uv.y, acc.y);
        acc.z = fmaf(v.z, uv.z, acc.z);
        acc.w = fmaf(v.w, uv.w, acc.w);
    }
    float s = (acc.x + acc.y) + (acc.z + acc.w);

#pragma unroll
    for (int off = 16; off > 0; off >>= 1)
        s += __shfl_xor_sync(0xffffffffu, s, off);

    __shared__ float red[8];
    if ((t & 31) == 0) red[t >> 5] = s;
    __syncthreads();
    if (t == 0) {
        float bs = 0.f;
#pragma unroll
        for (int i = 0; i < 8; ++i) bs += red[i];
        g_pz[blk] = bs;
    }

    __threadfence();
    __shared__ int s_last;
    if (t == 0) s_last = (atomicAdd(&g_ctrM, 1u) == NPZ - 1);
    __syncthreads();
    if (!s_last) return;
    __threadfence();

    // final: warp w (0..7) handles batch w; fixed order -> deterministic
    const int w = t >> 5, lane = t & 31;
    const float c = g_c;
    float z = 0.f;
#pragma unroll
    for (int i = lane; i < NCHUNK; i += 32) z += g_pz[w * NCHUNK + i];
#pragma unroll
    for (int off = 16; off > 0; off >>= 1)
        z += __shfl_xor_sync(0xffffffffu, z, off);
    if (lane == 0) {
        const float zz = z + c;
        out[w] = 1.0f / (1.0f + expf(-zz));
    }
    __syncthreads();
    if (t == 0) g_ctrM = 0;   // reset for next graph replay
}

// ---------------------------------------------------------------------------
// Inputs (metadata order): 0=x 1=Wq 2=bq 3=Wv 4=bv 5=Wr 6=br 7=Wl 8=bl
// Output: float32 [B]
// ---------------------------------------------------------------------------
extern "C" void kernel_launch(void* const* d_in, const int* in_sizes, int n_in,
                              void* d_out, int out_size) {
    const float* x  = (const float*)d_in[0];
    const float* Wr = (const float*)d_in[5];
    const float* br = (const float*)d_in[6];
    const float* Wl = (const float*)d_in[7];
    const float* bl = (const float*)d_in[8];
    float* out = (float*)d_out;

    kU<<<NUB, 128>>>(Wr, Wl, br, bl);
    kMain<<<NPZ, 256>>>(x, out);
}

// round 15
// speedup vs baseline: 1.4418x; 1.4197x over previous
#include <cuda_runtime.h>
#include <math.h>

// LogLinearAttention collapses analytically:
//   softmax over axis=1 (s) => sum_s attn[b,s,t] == 1
//   pooled[b,d] = sum_t r[b,t,d] = (sum_s x[b,s,:]) @ Wr^T + S*br
//   out[b] = sigmoid( sum_d xs[b,d]*u[d] + c ),  u = Wl @ Wr,  c = S*dot(br,Wl)+bl
//
// Two kernels. KEY FIX vs R12: the kernel-wide completion counter is a
// two-level atomic tree (32 padded counters -> 1 counter) instead of one
// global counter. Single-address L2 atomics serialize at ~27cyc/op; with
// 1024 blocks that alone was ~13us of kernel time.

#define BB 8
#define SS 2048
#define DD 512
#define D4 128               // float4 columns per row

// kWF: 16 blocks x 512 thr -> u = Wl @ Wr and c, last-block fold (cheap: 16 atomics)
#define WB 16
#define WSUB 4               // row subgroups per block (512 thr / 128 cols)
#define NPU (WB * WSUB)      // 64 partial vectors

// kMain: 512 blocks x 256 thr, 32 rows per block, 16 float4 loads per thread
#define MB 512
#define CPB 64               // chunk-blocks per batch
#define GROUPS 32            // level-1 counter groups
#define PER_GROUP (MB / GROUPS)  // 16 arrivals per level-1 counter

__device__ float g_pu[NPU * DD];        // u partials (128 KiB)
__device__ float g_u[DD];               // folded u
__device__ float g_c;                   // c = S*dot(br,Wl) + bl
__device__ float g_pz[MB];              // per-block scalar partial of z
__device__ unsigned int g_ctrW;                 // kWF counter (16 arrivals, fine)
__device__ unsigned int g_ctrA[GROUPS * 64];    // level-1, stride 256B (distinct LTS)
__device__ unsigned int g_ctrB;                 // level-2 (32 arrivals)

// ---------------------------------------------------------------------------
// kWF: block p covers Wr rows 32p..32p+31. Thread (col=t&127, sub=t>>7)
// accumulates 8 rows into a float4 partial. Last block folds 64 partials,
// writes g_u, computes g_c, resets counter.
// ---------------------------------------------------------------------------
__global__ void __launch_bounds__(512) kWF(const float* __restrict__ Wr,
                                           const float* __restrict__ Wl,
                                           const float* __restrict__ br,
                                           const float* __restrict__ bl) {
    const int p   = blockIdx.x;
    const int t   = threadIdx.x;
    const int col = t & (D4 - 1);
    const int sub = t >> 7;             // 0..3
    const int j0  = p * 32 + sub * 8;

    float4 acc = make_float4(0.f, 0.f, 0.f, 0.f);
#pragma unroll
    for (int jj = 0; jj < 8; ++jj) {
        const int j = j0 + jj;
        const float wl = __ldg(Wl + j);
        const float4 w = reinterpret_cast<const float4*>(Wr + (size_t)j * DD)[col];
        acc.x = fmaf(wl, w.x, acc.x);
        acc.y = fmaf(wl, w.y, acc.y);
        acc.z = fmaf(wl, w.z, acc.z);
        acc.w = fmaf(wl, w.w, acc.w);
    }
    reinterpret_cast<float4*>(g_pu + (size_t)(p * WSUB + sub) * DD)[col] = acc;

    __threadfence();
    __shared__ int s_last;
    if (t == 0) s_last = (atomicAdd(&g_ctrW, 1u) == WB - 1);
    __syncthreads();
    if (!s_last) return;
    __threadfence();

    // fold 64 partials: sub handles partials sub*16..sub*16+15 (fixed order)
    float4 f = make_float4(0.f, 0.f, 0.f, 0.f);
#pragma unroll
    for (int q = 0; q < 16; ++q) {
        const float4 v = reinterpret_cast<const float4*>(
            g_pu + (size_t)(sub * 16 + q) * DD)[col];
        f.x += v.x; f.y += v.y; f.z += v.z; f.w += v.w;
    }
    __shared__ float4 sm[WSUB][D4];     // 8 KiB
    sm[sub][col] = f;
    __syncthreads();
    if (sub == 0) {
        float4 u4;
        u4.x = ((sm[0][col].x + sm[1][col].x) + (sm[2][col].x + sm[3][col].x));
        u4.y = ((sm[0][col].y + sm[1][col].y) + (sm[2][col].y + sm[3][col].y));
        u4.z = ((sm[0][col].z + sm[1][col].z) + (sm[2][col].z + sm[3][col].z));
        u4.w = ((sm[0][col].w + sm[1][col].w) + (sm[2][col].w + sm[3][col].w));
        reinterpret_cast<float4*>(g_u)[col] = u4;
    }

    // c = S * dot(br, Wl) + bl  (512 threads, one element each)
    float pr = br[t] * Wl[t];
#pragma unroll
    for (int off = 16; off > 0; off >>= 1)
        pr += __shfl_xor_sync(0xffffffffu, pr, off);
    __shared__ float sdot[16];
    if ((t & 31) == 0) sdot[t >> 5] = pr;
    __syncthreads();
    if (t == 0) {
        float d = 0.f;
#pragma unroll
        for (int i = 0; i < 16; ++i) d += sdot[i];
        g_c = (float)SS * d + bl[0];
        g_ctrW = 0;                     // reset for next graph replay
    }
}

// ---------------------------------------------------------------------------
// kMain: 512 blocks x 256 thr. Block (b, ch) covers rows ch*32..+31 of batch b.
// Thread (col=t&127, sub=t>>7) does 16 independent float4 loads of x dotted
// with u. Block-reduce -> g_pz[blk]. Completion via two-level atomic tree;
// the single last block reduces 512 scalars, applies sigmoid, writes out.
// ---------------------------------------------------------------------------
__global__ void __launch_bounds__(256) kMain(const float* __restrict__ x,
                                             float* __restrict__ out) {
    const int blk = blockIdx.x;
    const int b   = blk >> 6;
    const int ch  = blk & (CPB - 1);
    const int t   = threadIdx.x;
    const int col = t & (D4 - 1);
    const int sub = t >> 7;             // 0 or 1

    const float4 uv = reinterpret_cast<const float4*>(g_u)[col];
    const float4* xp = reinterpret_cast<const float4*>(
        x + ((size_t)b * SS + (size_t)ch * 32 + (size_t)sub * 16) * DD);

    float4 a0 = make_float4(0.f, 0.f, 0.f, 0.f);
    float4 a1 = make_float4(0.f, 0.f, 0.f, 0.f);
#pragma unroll
    for (int r = 0; r < 8; ++r) {
        const float4 v0 = xp[(size_t)(2 * r)     * D4 + col];
        const float4 v1 = xp[(size_t)(2 * r + 1) * D4 + col];
        a0.x = fmaf(v0.x, uv.x, a0.x);
        a0.y = fmaf(v0.y, uv.y, a0.y);
        a0.z = fmaf(v0.z, uv.z, a0.z);
        a0.w = fmaf(v0.w, uv.w, a0.w);
        a1.x = fmaf(v1.x, uv.x, a1.x);
        a1.y = fmaf(v1.y, uv.y, a1.y);
        a1.z = fmaf(v1.z, uv.z, a1.z);
        a1.w = fmaf(v1.w, uv.w, a1.w);
    }
    float s = ((a0.x + a1.x) + (a0.y + a1.y)) + ((a0.z + a1.z) + (a0.w + a1.w));

#pragma unroll
    for (int off = 16; off > 0; off >>= 1)
        s += __shfl_xor_sync(0xffffffffu, s, off);

    __shared__ float red[8];
    if ((t & 31) == 0) red[t >> 5] = s;
    __syncthreads();
    if (t == 0) {
        float bs = 0.f;
#pragma unroll
        for (int i = 0; i < 8; ++i) bs += red[i];
        g_pz[blk] = bs;
    }

    __threadfence();
    __shared__ int s_last;
    if (t == 0) {
        s_last = 0;
        const int g = blk & (GROUPS - 1);
        if (atomicAdd(&g_ctrA[g * 64], 1u) == PER_GROUP - 1) {
            // group-last: arrive at level-2
            if (atomicAdd(&g_ctrB, 1u) == GROUPS - 1) s_last = 1;
        }
    }
    __syncthreads();
    if (!s_last) return;
    __threadfence();

    // final: warp w (0..7) handles batch w; fixed-order sums -> deterministic
    const int w = t >> 5, lane = t & 31;
    const float c = g_c;
    float z = g_pz[w * CPB + lane] + g_pz[w * CPB + 32 + lane];
#pragma unroll
    for (int off = 16; off > 0; off >>= 1)
        z += __shfl_xor_sync(0xffffffffu, z, off);
    if (lane == 0) {
        const float zz = z + c;
        out[w] = 1.0f / (1.0f + expf(-zz));
    }

    // reset counters for next graph replay
    if (t < GROUPS) g_ctrA[t * 64] = 0;
    if (t == 0) g_ctrB = 0;
}

// ---------------------------------------------------------------------------
// Inputs (metadata order): 0=x 1=Wq 2=bq 3=Wv 4=bv 5=Wr 6=br 7=Wl 8=bl
// Output: float32 [B]
// ---------------------------------------------------------------------------
extern "C" void kernel_launch(void* const* d_in, const int* in_sizes, int n_in,
                              void* d_out, int out_size) {
    const float* x  = (const float*)d_in[0];
    const float* Wr = (const float*)d_in[5];
    const float* br = (const float*)d_in[6];
    const float* Wl = (const float*)d_in[7];
    const float* bl = (const float*)d_in[8];
    float* out = (float*)d_out;

    kWF<<<WB, 512>>>(Wr, Wl, br, bl);
    kMain<<<MB, 256>>>(x, out);
}